// round 6
// baseline (speedup 1.0000x reference)
#include <cuda_runtime.h>
#include <math.h>
#include <stdint.h>

// ---------------------------------------------------------------------------
// Problem constants
// ---------------------------------------------------------------------------
#define BATCH 32
#define IMG   224
#define PATCH 16
#define DM    768
#define NH    12
#define HS    64
#define NL    12
#define TB    32
#define MLPD  3072
#define AOUT  7
#define NPATCH 196
#define SEQ   426
#define TOK   (BATCH*SEQ)   // 13632

// ---------------------------------------------------------------------------
// Scratch
// ---------------------------------------------------------------------------
__device__ float g_X  [TOK*DM];
__device__ float g_XN [TOK*DM];
__device__ float g_Q  [TOK*DM];
__device__ float g_K  [TOK*DM];
__device__ float g_V  [TOK*DM];
__device__ float g_ATT[TOK*DM];
__device__ float g_S  [(long long)BATCH*NH*SEQ*SEQ];
__device__ float g_H  [TOK*MLPD];
__device__ float g_P  [BATCH*NPATCH*DM];
__device__ float g_CLS[BATCH*DM];
__device__ float g_HID[BATCH*4*DM];

// ---------------------------------------------------------------------------
// TF32 helpers
// ---------------------------------------------------------------------------
__device__ __forceinline__ uint32_t f2tf32(float f) {
    uint32_t r;
    asm("cvt.rna.tf32.f32 %0, %1;" : "=r"(r) : "f"(f));
    return r;
}

__device__ __forceinline__ void mma_tf32(float (&d)[4], const uint32_t (&a)[4],
                                         const uint32_t (&b)[2]) {
    asm volatile(
        "mma.sync.aligned.m16n8k8.row.col.f32.tf32.tf32.f32 "
        "{%0,%1,%2,%3}, {%4,%5,%6,%7}, {%8,%9}, {%0,%1,%2,%3};"
        : "+f"(d[0]), "+f"(d[1]), "+f"(d[2]), "+f"(d[3])
        : "r"(a[0]), "r"(a[1]), "r"(a[2]), "r"(a[3]), "r"(b[0]), "r"(b[1]));
}

// ---------------------------------------------------------------------------
// TF32 tensor-core GEMM, vectorized loads + paired-B smem (LDS.64 fragments).
//   C = alpha*A*B (+bias)(+C)(relu), batched over z.
//   A: MxK row-major (lda). B: normal KxN (ldb); TRANSB NxK (B^T);
//      BHEAD B[k,n] at (n>>6)*ldb + k*64 + (n&63)  (per-head [D,64] packs).
//   CTA tile 128 x BN, BK=16. 8 warps: warp_m=(w&3)*32, warp_n=(w>>2)*(BN/2).
//   B smem layout: per n-row 40 words; element (n,k) at
//     n*40 + ((k>>3)*4 + (k&3))*2 + ((k>>2)&1)
//   so (k, k+4) are adjacent words -> consumer does one LDS.64 per fragment.
//   LDB=40 => 8B-bank pattern (stride 20 = 4 mod 16) is conflict-free.
// ---------------------------------------------------------------------------
#define SLD 20   // A smem leading dim (16 + 4 pad)
#define LDB 40   // B smem words per n-row

template<int BN, bool TRANSB, bool BHEAD, bool RELU, bool ACCUM, bool BIAS>
__global__ void __launch_bounds__(256)
gemm_tf32(const float* __restrict__ A, const float* __restrict__ B,
          float* __restrict__ C, const float* __restrict__ bias,
          int M, int N, int K, int lda, int ldb, int ldc, float alpha,
          int ndiv, long long s1A, long long s2A, long long s1B, long long s2B,
          long long s1C, long long s2C)
{
    constexpr int NT = (BN / 2) / 8;       // n-tiles per warp (8 or 4)
    __shared__ uint32_t As[128][SLD];
    __shared__ uint32_t Bp[BN * LDB];

    const int z  = blockIdx.z;
    const int z1 = z / ndiv, z2 = z % ndiv;
    A += (long long)z1 * s1A + (long long)z2 * s2A;
    B += (long long)z1 * s1B + (long long)z2 * s2B;
    C += (long long)z1 * s1C + (long long)z2 * s2C;

    const int tid    = threadIdx.x;
    const int wid    = tid >> 5;
    const int lane   = tid & 31;
    const int g      = lane >> 2;
    const int tg     = lane & 3;
    const int warp_m = (wid & 3) * 32;
    const int warp_n = (wid >> 2) * (BN / 2);
    const int row0   = blockIdx.y * 128;
    const int col0   = blockIdx.x * BN;

    const bool A4 = ((lda & 3) == 0);
    const bool B4 = ((ldb & 3) == 0);

    float acc[2][NT][4];
    #pragma unroll
    for (int mt = 0; mt < 2; mt++)
        #pragma unroll
        for (int nt = 0; nt < NT; nt++)
            #pragma unroll
            for (int i = 0; i < 4; i++) acc[mt][nt][i] = 0.f;

    for (int kt = 0; kt < K; kt += 16) {
        // ---- A tile: 128 x 16, thread loads float4 along k ----
        #pragma unroll
        for (int i = 0; i < 2; i++) {
            int e  = tid + i * 256;
            int r  = e >> 2;
            int kq = (e & 3) * 4;
            int gr = row0 + r, gk = kt + kq;
            float v[4] = {0.f, 0.f, 0.f, 0.f};
            if (gr < M) {
                const float* p = A + (long long)gr * lda + gk;
                int kmax = K - gk;
                if (A4 && kmax >= 4) {
                    float4 t = *(const float4*)p;
                    v[0] = t.x; v[1] = t.y; v[2] = t.z; v[3] = t.w;
                } else {
                    #pragma unroll
                    for (int j = 0; j < 4; j++) if (j < kmax) v[j] = p[j];
                }
            }
            #pragma unroll
            for (int j = 0; j < 4; j++) As[r][kq + j] = f2tf32(v[j]);
        }

        // ---- B tile: BN x 16 into paired layout ----
        if (TRANSB) {
            #pragma unroll
            for (int i = 0; i < BN / 64; i++) {
                int e  = tid + i * 256;
                int n  = e >> 2;
                int kq = (e & 3) * 4;
                int gn = col0 + n, gk = kt + kq;
                float v[4] = {0.f, 0.f, 0.f, 0.f};
                if (gn < N) {
                    const float* p = B + (long long)gn * ldb + gk;
                    int kmax = K - gk;
                    if (B4 && kmax >= 4) {
                        float4 t = *(const float4*)p;
                        v[0] = t.x; v[1] = t.y; v[2] = t.z; v[3] = t.w;
                    } else {
                        #pragma unroll
                        for (int j = 0; j < 4; j++) if (j < kmax) v[j] = p[j];
                    }
                }
                #pragma unroll
                for (int j = 0; j < 4; j++) {
                    int k = kq + j;
                    Bp[n * LDB + ((k >> 3) * 4 + (k & 3)) * 2 + ((k >> 2) & 1)] = f2tf32(v[j]);
                }
            }
        } else {
            #pragma unroll
            for (int i = 0; i < BN / 64; i++) {
                int e   = tid + i * 256;
                int idx = e * 4;
                int n   = idx & (BN - 1);
                int k   = idx / BN;
                int gn  = col0 + n, gk = kt + k;
                float v[4] = {0.f, 0.f, 0.f, 0.f};
                if (gk < K) {
                    long long off;
                    if (BHEAD) off = (long long)(gn >> 6) * ldb + (long long)gk * 64 + (gn & 63);
                    else       off = (long long)gk * ldb + gn;
                    const float* p = B + off;
                    int nmax = N - gn;
                    if (B4 && nmax >= 4) {
                        float4 t = *(const float4*)p;
                        v[0] = t.x; v[1] = t.y; v[2] = t.z; v[3] = t.w;
                    } else {
                        #pragma unroll
                        for (int j = 0; j < 4; j++) if (j < nmax) v[j] = p[j];
                    }
                }
                uint32_t wbase = ((k >> 3) * 4 + (k & 3)) * 2 + ((k >> 2) & 1);
                #pragma unroll
                for (int j = 0; j < 4; j++)
                    Bp[(n + j) * LDB + wbase] = f2tf32(v[j]);
            }
        }
        __syncthreads();

        // ---- MMA: 2 k-steps of 8 ----
        #pragma unroll
        for (int ks = 0; ks < 2; ks++) {
            const int kk = ks * 8;
            uint32_t af[2][4];
            #pragma unroll
            for (int mt = 0; mt < 2; mt++) {
                int rs = warp_m + mt * 16 + g;
                af[mt][0] = As[rs][kk + tg];
                af[mt][1] = As[rs + 8][kk + tg];
                af[mt][2] = As[rs][kk + tg + 4];
                af[mt][3] = As[rs + 8][kk + tg + 4];
            }
            uint32_t bf[NT][2];
            #pragma unroll
            for (int nt = 0; nt < NT; nt++) {
                int cs = warp_n + nt * 8 + g;
                uint2 bb = *(const uint2*)&Bp[cs * LDB + (ks * 4 + tg) * 2];
                bf[nt][0] = bb.x; bf[nt][1] = bb.y;
            }
            #pragma unroll
            for (int mt = 0; mt < 2; mt++)
                #pragma unroll
                for (int nt = 0; nt < NT; nt++)
                    mma_tf32(acc[mt][nt], af[mt], bf[nt]);
        }
        __syncthreads();
    }

    // ---- epilogue ----
    #pragma unroll
    for (int mt = 0; mt < 2; mt++) {
        #pragma unroll
        for (int nt = 0; nt < NT; nt++) {
            int r_base = row0 + warp_m + mt * 16 + g;
            int c_base = col0 + warp_n + nt * 8 + tg * 2;
            #pragma unroll
            for (int h = 0; h < 2; h++) {
                int r = r_base + h * 8;
                if (r >= M) continue;
                #pragma unroll
                for (int j = 0; j < 2; j++) {
                    int c = c_base + j;
                    if (c >= N) continue;
                    float v = acc[mt][nt][h * 2 + j] * alpha;
                    if (BIAS) v += bias[c];
                    long long ci = (long long)r * ldc + c;
                    if (ACCUM) v += C[ci];
                    if (RELU)  v = fmaxf(v, 0.f);
                    C[ci] = v;
                }
            }
        }
    }
}

// ---------------------------------------------------------------------------
// LayerNorm: one block per row of 768
// ---------------------------------------------------------------------------
__global__ void __launch_bounds__(256)
ln_k(const float* __restrict__ x, float* __restrict__ out,
     const float* __restrict__ g, const float* __restrict__ b,
     long long strideIn, long long strideOut)
{
    long long r = blockIdx.x;
    const float* xr = x + r * strideIn;
    float* orow = out + r * strideOut;

    float s = 0.f, s2 = 0.f;
    for (int i = threadIdx.x; i < DM; i += 256) {
        float v = xr[i]; s += v; s2 += v * v;
    }
    for (int o = 16; o; o >>= 1) {
        s  += __shfl_down_sync(0xffffffffu, s,  o);
        s2 += __shfl_down_sync(0xffffffffu, s2, o);
    }
    __shared__ float shs[8], shs2[8];
    int w = threadIdx.x >> 5, ln = threadIdx.x & 31;
    if (ln == 0) { shs[w] = s; shs2[w] = s2; }
    __syncthreads();
    __shared__ float sh_m, sh_inv;
    if (threadIdx.x == 0) {
        float S = 0.f, S2 = 0.f;
        #pragma unroll
        for (int i = 0; i < 8; i++) { S += shs[i]; S2 += shs2[i]; }
        float m = S / (float)DM;
        float var = S2 / (float)DM - m * m;
        sh_m = m; sh_inv = rsqrtf(var + 1e-5f);
    }
    __syncthreads();
    float m = sh_m, inv = sh_inv;
    for (int i = threadIdx.x; i < DM; i += 256)
        orow[i] = (xr[i] - m) * inv * g[i] + b[i];
}

// ---------------------------------------------------------------------------
// Row softmax over 426 elements (in-place)
// ---------------------------------------------------------------------------
__global__ void __launch_bounds__(128)
softmax_k(float* __restrict__ s)
{
    long long r = blockIdx.x;
    float* row = s + r * (long long)SEQ;
    int t = threadIdx.x;

    float v[4];
    float mx = -1e30f;
    #pragma unroll
    for (int j = 0; j < 4; j++) {
        int i = t + j * 128;
        v[j] = (i < SEQ) ? row[i] : -1e30f;
        mx = fmaxf(mx, v[j]);
    }
    for (int o = 16; o; o >>= 1) mx = fmaxf(mx, __shfl_xor_sync(0xffffffffu, mx, o));
    __shared__ float shm[4], shsum[4];
    if ((t & 31) == 0) shm[t >> 5] = mx;
    __syncthreads();
    float gmx = fmaxf(fmaxf(shm[0], shm[1]), fmaxf(shm[2], shm[3]));

    float sum = 0.f;
    #pragma unroll
    for (int j = 0; j < 4; j++) { v[j] = expf(v[j] - gmx); sum += v[j]; }
    for (int o = 16; o; o >>= 1) sum += __shfl_xor_sync(0xffffffffu, sum, o);
    if ((t & 31) == 0) shsum[t >> 5] = sum;
    __syncthreads();
    float inv = 1.f / (shsum[0] + shsum[1] + shsum[2] + shsum[3]);

    #pragma unroll
    for (int j = 0; j < 4; j++) {
        int i = t + j * 128;
        if (i < SEQ) row[i] = v[j] * inv;
    }
}

// ---------------------------------------------------------------------------
// Patchify / scatter / embed
// ---------------------------------------------------------------------------
__global__ void patchify_k(const float* __restrict__ img, float* __restrict__ P)
{
    int idx = blockIdx.x * blockDim.x + threadIdx.x;
    if (idx >= BATCH * NPATCH * DM) return;
    int d = idx % DM;
    int p = (idx / DM) % NPATCH;
    int b = idx / (DM * NPATCH);
    int c   = d % 3;
    int pix = d / 3;
    int px  = pix % PATCH, py = pix / PATCH;
    int pw  = p % 14,      ph = p / 14;
    int row = ph * PATCH + py, col = pw * PATCH + px;
    P[idx] = img[(((long long)b * IMG + row) * IMG + col) * 3 + c];
}

__global__ void scatter_patch_k(const float* __restrict__ G, float* __restrict__ X,
                                const float* __restrict__ pb,
                                const float* __restrict__ pos, int tokoff)
{
    int idx = blockIdx.x * blockDim.x + threadIdx.x;
    if (idx >= BATCH * NPATCH * DM) return;
    int d = idx % DM;
    int r = idx / DM;
    int b = r / NPATCH, p = r % NPATCH;
    int t = tokoff + p;
    X[((long long)b * SEQ + t) * DM + d] = G[idx] + pb[d] + pos[(long long)t * DM + d];
}

__global__ void embed_special_k(float* __restrict__ X,
                                const float* __restrict__ cls,
                                const float* __restrict__ goal,
                                const float* __restrict__ tok_emb,
                                const int*   __restrict__ txt,
                                const float* __restrict__ pos)
{
    int idx = blockIdx.x * blockDim.x + threadIdx.x;
    if (idx >= BATCH * 34 * DM) return;
    int d = idx % DM;
    int s = (idx / DM) % 34;
    int b = idx / (DM * 34);
    int t; float v;
    if (s == 0)      { t = 0;   v = cls[d];  }
    else if (s == 1) { t = 197; v = goal[d]; }
    else {
        t = 394 + (s - 2);
        v = tok_emb[(long long)txt[b * TB + (s - 2)] * DM + d];
    }
    X[((long long)b * SEQ + t) * DM + d] = v + pos[(long long)t * DM + d];
}

// ---------------------------------------------------------------------------
// Host driver
// ---------------------------------------------------------------------------
static inline dim3 ggrid(int M, int N, int BN, int bz)
{
    return dim3((unsigned)((N + BN - 1) / BN), (unsigned)((M + 127) / 128), (unsigned)bz);
}

extern "C" void kernel_launch(void* const* d_in, const int* in_sizes, int n_in,
                              void* d_out, int out_size)
{
    (void)in_sizes; (void)n_in; (void)out_size;

    const float* images    = (const float*)d_in[0];
    const float* goal_imgs = (const float*)d_in[1];
    const int*   goals_txt = (const int*)  d_in[2];
    const float* patch_W   = (const float*)d_in[3];
    const float* patch_b   = (const float*)d_in[4];
    const float* tok_emb   = (const float*)d_in[5];
    const float* pos_emb   = (const float*)d_in[6];
    const float* cls_tok   = (const float*)d_in[7];
    const float* goal_tok  = (const float*)d_in[8];
    const float* Wq        = (const float*)d_in[9];
    const float* Wk        = (const float*)d_in[10];
    const float* Wv        = (const float*)d_in[11];
    const float* Wo        = (const float*)d_in[12];
    const float* bo        = (const float*)d_in[13];
    const float* ln1_g     = (const float*)d_in[14];
    const float* ln1_b     = (const float*)d_in[15];
    const float* ln2_g     = (const float*)d_in[16];
    const float* ln2_b     = (const float*)d_in[17];
    const float* W1        = (const float*)d_in[18];
    const float* b1        = (const float*)d_in[19];
    const float* W2        = (const float*)d_in[20];
    const float* b2        = (const float*)d_in[21];
    const float* lnf_g     = (const float*)d_in[22];
    const float* lnf_b     = (const float*)d_in[23];
    const float* ah_W1     = (const float*)d_in[24];
    const float* ah_b1     = (const float*)d_in[25];
    const float* ah_W2     = (const float*)d_in[26];
    const float* ah_b2     = (const float*)d_in[27];
    float* out = (float*)d_out;

    float *X, *XN, *Qf, *Kf, *Vf, *ATT, *S, *H, *P, *CLS, *HID;
    cudaGetSymbolAddress((void**)&X,   g_X);
    cudaGetSymbolAddress((void**)&XN,  g_XN);
    cudaGetSymbolAddress((void**)&Qf,  g_Q);
    cudaGetSymbolAddress((void**)&Kf,  g_K);
    cudaGetSymbolAddress((void**)&Vf,  g_V);
    cudaGetSymbolAddress((void**)&ATT, g_ATT);
    cudaGetSymbolAddress((void**)&S,   g_S);
    cudaGetSymbolAddress((void**)&H,   g_H);
    cudaGetSymbolAddress((void**)&P,   g_P);
    cudaGetSymbolAddress((void**)&CLS, g_CLS);
    cudaGetSymbolAddress((void**)&HID, g_HID);

    const float scale = 0.03608439182435161f; // 768^-0.5
    const int PTOT = BATCH * NPATCH * DM;

    // --- Embedding ---------------------------------------------------------
    patchify_k<<<(PTOT + 255) / 256, 256>>>(images, P);
    gemm_tf32<128,false,false,false,false,false><<<ggrid(BATCH*NPATCH, DM, 128, 1), 256>>>(
        P, patch_W, H, nullptr, BATCH*NPATCH, DM, DM, DM, DM, DM, 1.f,
        1, 0,0, 0,0, 0,0);
    scatter_patch_k<<<(PTOT + 255) / 256, 256>>>(H, X, patch_b, pos_emb, 1);

    patchify_k<<<(PTOT + 255) / 256, 256>>>(goal_imgs, P);
    gemm_tf32<128,false,false,false,false,false><<<ggrid(BATCH*NPATCH, DM, 128, 1), 256>>>(
        P, patch_W, H, nullptr, BATCH*NPATCH, DM, DM, DM, DM, DM, 1.f,
        1, 0,0, 0,0, 0,0);
    scatter_patch_k<<<(PTOT + 255) / 256, 256>>>(H, X, patch_b, pos_emb, 198);

    embed_special_k<<<(BATCH*34*DM + 255) / 256, 256>>>(
        X, cls_tok, goal_tok, tok_emb, goals_txt, pos_emb);

    // --- Transformer layers ------------------------------------------------
    for (int l = 0; l < NL; l++) {
        const float* Wq_l  = Wq + (long long)l * NH * DM * HS;
        const float* Wk_l  = Wk + (long long)l * NH * DM * HS;
        const float* Wv_l  = Wv + (long long)l * NH * DM * HS;
        const float* Wo_l  = Wo + (long long)l * DM * DM;
        const float* bo_l  = bo + (long long)l * DM;
        const float* l1g   = ln1_g + (long long)l * DM;
        const float* l1b   = ln1_b + (long long)l * DM;
        const float* l2g   = ln2_g + (long long)l * DM;
        const float* l2b   = ln2_b + (long long)l * DM;
        const float* W1_l  = W1 + (long long)l * DM * MLPD;
        const float* b1_l  = b1 + (long long)l * MLPD;
        const float* W2_l  = W2 + (long long)l * MLPD * DM;
        const float* b2_l  = b2 + (long long)l * DM;

        ln_k<<<TOK, 256>>>(X, XN, l1g, l1b, DM, DM);

        // Q/K/V as single N=768 GEMMs with head-packed B addressing
        gemm_tf32<128,false,true,false,false,false><<<ggrid(TOK, DM, 128, 1), 256>>>(
            XN, Wq_l, Qf, nullptr, TOK, DM, DM, DM, DM*HS, DM, 1.f,
            1, 0,0, 0,0, 0,0);
        gemm_tf32<128,false,true,false,false,false><<<ggrid(TOK, DM, 128, 1), 256>>>(
            XN, Wk_l, Kf, nullptr, TOK, DM, DM, DM, DM*HS, DM, 1.f,
            1, 0,0, 0,0, 0,0);
        gemm_tf32<128,false,true,false,false,false><<<ggrid(TOK, DM, 128, 1), 256>>>(
            XN, Wv_l, Vf, nullptr, TOK, DM, DM, DM, DM*HS, DM, 1.f,
            1, 0,0, 0,0, 0,0);

        // scores[z=(b,h)] = scale * Q @ K^T   (426x426, K=64)
        gemm_tf32<128,true,false,false,false,false><<<ggrid(SEQ, SEQ, 128, BATCH*NH), 256>>>(
            Qf, Kf, S, nullptr, SEQ, SEQ, HS, DM, DM, SEQ, scale,
            NH, (long long)SEQ*DM, HS, (long long)SEQ*DM, HS,
                (long long)NH*SEQ*SEQ, (long long)SEQ*SEQ);

        softmax_k<<<BATCH*NH*SEQ, 128>>>(S);

        // att[z=(b,h)] = W @ V   (426x64, K=426)  (A has lda=426 -> scalar path)
        gemm_tf32<64,false,false,false,false,false><<<ggrid(SEQ, HS, 64, BATCH*NH), 256>>>(
            S, Vf, ATT, nullptr, SEQ, HS, SEQ, SEQ, DM, DM, 1.f,
            NH, (long long)NH*SEQ*SEQ, (long long)SEQ*SEQ,
                (long long)SEQ*DM, HS, (long long)SEQ*DM, HS);

        // X += ATT @ Wo + bo
        gemm_tf32<128,false,false,false,true,true><<<ggrid(TOK, DM, 128, 1), 256>>>(
            ATT, Wo_l, X, bo_l, TOK, DM, DM, DM, DM, DM, 1.f,
            1, 0,0, 0,0, 0,0);

        ln_k<<<TOK, 256>>>(X, XN, l2g, l2b, DM, DM);

        // H = relu(XN @ W1 + b1)
        gemm_tf32<128,false,false,true,false,true><<<ggrid(TOK, MLPD, 128, 1), 256>>>(
            XN, W1_l, H, b1_l, TOK, MLPD, DM, DM, MLPD, MLPD, 1.f,
            1, 0,0, 0,0, 0,0);

        // X += H @ W2 + b2
        gemm_tf32<128,false,false,false,true,true><<<ggrid(TOK, DM, 128, 1), 256>>>(
            H, W2_l, X, b2_l, TOK, DM, MLPD, MLPD, DM, DM, 1.f,
            1, 0,0, 0,0, 0,0);
    }

    // --- Final LN (cls rows only) + action head ---------------------------
    ln_k<<<BATCH, 256>>>(X, CLS, lnf_g, lnf_b, (long long)SEQ * DM, DM);

    gemm_tf32<128,false,false,true,false,true><<<ggrid(BATCH, 4*DM, 128, 1), 256>>>(
        CLS, ah_W1, HID, ah_b1, BATCH, 4*DM, DM, DM, 4*DM, 4*DM, 1.f,
        1, 0,0, 0,0, 0,0);

    gemm_tf32<64,false,false,false,false,true><<<ggrid(BATCH, AOUT, 64, 1), 256>>>(
        HID, ah_W2, out, ah_b2, BATCH, AOUT, 4*DM, 4*DM, AOUT, AOUT, 1.f,
        1, 0,0, 0,0, 0,0);
}

// round 7
// speedup vs baseline: 1.9242x; 1.9242x over previous
#include <cuda_runtime.h>
#include <math.h>
#include <stdint.h>

// ---------------------------------------------------------------------------
// Problem constants
// ---------------------------------------------------------------------------
#define BATCH 32
#define IMG   224
#define PATCH 16
#define DM    768
#define NH    12
#define HS    64
#define NL    12
#define TB    32
#define MLPD  3072
#define AOUT  7
#define NPATCH 196
#define SEQ   426
#define TOK   (BATCH*SEQ)   // 13632
#define SCALE 0.03608439182435161f  // 768^-0.5 (reference uses D^-0.5)

// ---------------------------------------------------------------------------
// Scratch
// ---------------------------------------------------------------------------
__device__ float g_X  [TOK*DM];
__device__ float g_XN [TOK*DM];
__device__ float g_Q  [TOK*DM];
__device__ float g_K  [TOK*DM];
__device__ float g_V  [TOK*DM];
__device__ float g_ATT[TOK*DM];
__device__ float g_H  [TOK*MLPD];
__device__ float g_P  [BATCH*NPATCH*DM];
__device__ float g_CLS[BATCH*DM];
__device__ float g_HID[BATCH*4*DM];

// ---------------------------------------------------------------------------
// TF32 helpers
// ---------------------------------------------------------------------------
__device__ __forceinline__ uint32_t f2tf32(float f) {
    uint32_t r;
    asm("cvt.rna.tf32.f32 %0, %1;" : "=r"(r) : "f"(f));
    return r;
}

__device__ __forceinline__ void mma_tf32(float (&d)[4], const uint32_t (&a)[4],
                                         const uint32_t (&b)[2]) {
    asm volatile(
        "mma.sync.aligned.m16n8k8.row.col.f32.tf32.tf32.f32 "
        "{%0,%1,%2,%3}, {%4,%5,%6,%7}, {%8,%9}, {%0,%1,%2,%3};"
        : "+f"(d[0]), "+f"(d[1]), "+f"(d[2]), "+f"(d[3])
        : "r"(a[0]), "r"(a[1]), "r"(a[2]), "r"(a[3]), "r"(b[0]), "r"(b[1]));
}

// ---------------------------------------------------------------------------
// TF32 tensor-core GEMM (R2 version — proven best).
// ---------------------------------------------------------------------------
#define SLD 20   // smem leading dim (16 + 4 pad)

template<int BN, bool TRANSB, bool BHEAD, bool RELU, bool ACCUM, bool BIAS>
__global__ void __launch_bounds__(256)
gemm_tf32(const float* __restrict__ A, const float* __restrict__ B,
          float* __restrict__ C, const float* __restrict__ bias,
          int M, int N, int K, int lda, int ldb, int ldc, float alpha,
          int ndiv, long long s1A, long long s2A, long long s1B, long long s2B,
          long long s1C, long long s2C)
{
    constexpr int NT = (BN / 2) / 8;
    __shared__ uint32_t As[128][SLD];
    __shared__ uint32_t Bs[BN][SLD];

    const int z  = blockIdx.z;
    const int z1 = z / ndiv, z2 = z % ndiv;
    A += (long long)z1 * s1A + (long long)z2 * s2A;
    B += (long long)z1 * s1B + (long long)z2 * s2B;
    C += (long long)z1 * s1C + (long long)z2 * s2C;

    const int tid    = threadIdx.x;
    const int wid    = tid >> 5;
    const int lane   = tid & 31;
    const int g      = lane >> 2;
    const int tg     = lane & 3;
    const int warp_m = (wid & 3) * 32;
    const int warp_n = (wid >> 2) * (BN / 2);
    const int row0   = blockIdx.y * 128;
    const int col0   = blockIdx.x * BN;

    float acc[2][NT][4];
    #pragma unroll
    for (int mt = 0; mt < 2; mt++)
        #pragma unroll
        for (int nt = 0; nt < NT; nt++)
            #pragma unroll
            for (int i = 0; i < 4; i++) acc[mt][nt][i] = 0.f;

    for (int kt = 0; kt < K; kt += 16) {
        #pragma unroll
        for (int i = 0; i < 2; i++) {
            int idx = tid + i * 256;
            int r   = idx >> 2;
            int kq  = (idx & 3) * 4;
            int gr  = row0 + r;
            const float* ap = A + (long long)gr * lda + kt + kq;
            #pragma unroll
            for (int j = 0; j < 4; j++) {
                int gk = kt + kq + j;
                float v = (gr < M && gk < K) ? ap[j] : 0.f;
                As[r][kq + j] = f2tf32(v);
            }
        }
        if (TRANSB) {
            constexpr int ELEMS = BN * 16 / 256;
            #pragma unroll
            for (int i = 0; i < ELEMS; i++) {
                int idx = tid + i * 256;
                int k   = idx & 15;
                int n   = idx >> 4;
                int gk  = kt + k, gn = col0 + n;
                float v = (gk < K && gn < N) ? B[(long long)gn * ldb + gk] : 0.f;
                Bs[n][k] = f2tf32(v);
            }
        } else {
            constexpr int ELEMS = BN * 16 / 256;
            #pragma unroll
            for (int i = 0; i < ELEMS; i++) {
                int idx = tid + i * 256;
                int n   = idx % BN;
                int k   = idx / BN;
                int gk  = kt + k, gn = col0 + n;
                float v = 0.f;
                if (gk < K && gn < N) {
                    long long off;
                    if (BHEAD) off = (long long)(gn >> 6) * ldb + (long long)gk * 64 + (gn & 63);
                    else       off = (long long)gk * ldb + gn;
                    v = B[off];
                }
                Bs[n][k] = f2tf32(v);
            }
        }
        __syncthreads();

        #pragma unroll
        for (int kk = 0; kk < 16; kk += 8) {
            uint32_t af[2][4];
            #pragma unroll
            for (int mt = 0; mt < 2; mt++) {
                int rs = warp_m + mt * 16 + g;
                af[mt][0] = As[rs][kk + tg];
                af[mt][1] = As[rs + 8][kk + tg];
                af[mt][2] = As[rs][kk + tg + 4];
                af[mt][3] = As[rs + 8][kk + tg + 4];
            }
            uint32_t bf[NT][2];
            #pragma unroll
            for (int nt = 0; nt < NT; nt++) {
                int cs = warp_n + nt * 8 + g;
                bf[nt][0] = Bs[cs][kk + tg];
                bf[nt][1] = Bs[cs][kk + tg + 4];
            }
            #pragma unroll
            for (int mt = 0; mt < 2; mt++)
                #pragma unroll
                for (int nt = 0; nt < NT; nt++)
                    mma_tf32(acc[mt][nt], af[mt], bf[nt]);
        }
        __syncthreads();
    }

    #pragma unroll
    for (int mt = 0; mt < 2; mt++) {
        #pragma unroll
        for (int nt = 0; nt < NT; nt++) {
            int r_base = row0 + warp_m + mt * 16 + g;
            int c_base = col0 + warp_n + nt * 8 + tg * 2;
            #pragma unroll
            for (int h = 0; h < 2; h++) {
                int r = r_base + h * 8;
                if (r >= M) continue;
                #pragma unroll
                for (int j = 0; j < 2; j++) {
                    int c = c_base + j;
                    if (c >= N) continue;
                    float v = acc[mt][nt][h * 2 + j] * alpha;
                    if (BIAS) v += bias[c];
                    long long ci = (long long)r * ldc + c;
                    if (ACCUM) v += C[ci];
                    if (RELU)  v = fmaxf(v, 0.f);
                    C[ci] = v;
                }
            }
        }
    }
}

// ---------------------------------------------------------------------------
// Fused flash attention.  Grid: (4 q-tiles, BATCH*NH).  256 threads.
//   Q/K/V flat [(b,t), h*64+e].  Output ATT same layout.
//   Online softmax; S never leaves the SM.  All tiles stride 68 words
//   (68 mod 32 = 4 -> fragment gathers conflict-free).
// ---------------------------------------------------------------------------
#define FLASH_SMEM_WORDS (8704 + 4352 + 4352 + 8704 + 256 + 256 + 128 + 128)

__global__ void __launch_bounds__(256)
flash_attn_k(const float* __restrict__ Qf, const float* __restrict__ Kf,
             const float* __restrict__ Vf, float* __restrict__ ATT)
{
    extern __shared__ uint32_t fsm[];
    uint32_t* Qs   = fsm;               // [128][68]
    uint32_t* Ks   = Qs + 128 * 68;     // [64][68]   key-major
    uint32_t* Vs   = Ks + 64 * 68;      // [64][68]   dim-major (V^T)
    uint32_t* Ps   = Vs + 64 * 68;      // [128][68]
    float* red_m   = (float*)(Ps + 128 * 68);  // [2][128]
    float* red_l   = red_m + 256;              // [2][128]
    float* row_m   = red_l + 256;              // [128]
    float* row_l   = row_m + 128;              // [128]

    const int z  = blockIdx.y;
    const int b  = z / NH, h = z % NH;
    const int q0 = blockIdx.x * 128;

    const int tid  = threadIdx.x;
    const int wid  = tid >> 5;
    const int lane = tid & 31;
    const int g    = lane >> 2;
    const int tg   = lane & 3;
    const int warp_m = (wid & 3) * 32;
    const int warp_n = (wid >> 2) * 32;
    const int colgrp = wid >> 2;

    // ---- load Q tile ----
    for (int i = tid; i < 128 * 64; i += 256) {
        int r = i >> 6, d = i & 63;
        int t = q0 + r;
        float v = (t < SEQ) ? Qf[((long long)(b * SEQ + t)) * DM + h * HS + d] : 0.f;
        Qs[r * 68 + d] = f2tf32(v);
    }
    if (tid < 128) { row_m[tid] = -1e30f; row_l[tid] = 0.f; }

    float oacc[2][4][4] = {};
    __syncthreads();

    for (int kt0 = 0; kt0 < SEQ; kt0 += 64) {
        // ---- load K (key-major) and V (dim-major) tiles ----
        for (int i = tid; i < 64 * 64; i += 256) {
            int kk = i >> 6, d = i & 63;
            int t = kt0 + kk;
            float kv = 0.f, vv = 0.f;
            if (t < SEQ) {
                long long base = ((long long)(b * SEQ + t)) * DM + h * HS + d;
                kv = Kf[base];
                vv = Vf[base];
            }
            Ks[kk * 68 + d] = f2tf32(kv);
            Vs[d * 68 + kk] = f2tf32(vv);
        }
        __syncthreads();

        // ---- S = Q @ K^T ----
        float sacc[2][4][4] = {};
        #pragma unroll
        for (int ks = 0; ks < 8; ks++) {
            const int kk = ks * 8;
            uint32_t af[2][4];
            #pragma unroll
            for (int mt = 0; mt < 2; mt++) {
                int rs = warp_m + mt * 16 + g;
                af[mt][0] = Qs[rs * 68 + kk + tg];
                af[mt][1] = Qs[(rs + 8) * 68 + kk + tg];
                af[mt][2] = Qs[rs * 68 + kk + tg + 4];
                af[mt][3] = Qs[(rs + 8) * 68 + kk + tg + 4];
            }
            uint32_t bf[4][2];
            #pragma unroll
            for (int nt = 0; nt < 4; nt++) {
                int cs = warp_n + nt * 8 + g;
                bf[nt][0] = Ks[cs * 68 + kk + tg];
                bf[nt][1] = Ks[cs * 68 + kk + tg + 4];
            }
            #pragma unroll
            for (int mt = 0; mt < 2; mt++)
                #pragma unroll
                for (int nt = 0; nt < 4; nt++)
                    mma_tf32(sacc[mt][nt], af[mt], bf[nt]);
        }

        // ---- scale + mask + partial row max ----
        #pragma unroll
        for (int mt = 0; mt < 2; mt++) {
            #pragma unroll
            for (int hh = 0; hh < 2; hh++) {
                float pm = -1e30f;
                #pragma unroll
                for (int nt = 0; nt < 4; nt++) {
                    #pragma unroll
                    for (int j = 0; j < 2; j++) {
                        int kglob = kt0 + warp_n + nt * 8 + tg * 2 + j;
                        float s = (kglob < SEQ) ? sacc[mt][nt][hh * 2 + j] * SCALE : -1e30f;
                        sacc[mt][nt][hh * 2 + j] = s;
                        pm = fmaxf(pm, s);
                    }
                }
                pm = fmaxf(pm, __shfl_xor_sync(0xffffffffu, pm, 1));
                pm = fmaxf(pm, __shfl_xor_sync(0xffffffffu, pm, 2));
                if (tg == 0)
                    red_m[colgrp * 128 + warp_m + mt * 16 + hh * 8 + g] = pm;
            }
        }
        __syncthreads();

        // ---- P = exp(s - m_new); rescale O; partial sums ----
        #pragma unroll
        for (int mt = 0; mt < 2; mt++) {
            #pragma unroll
            for (int hh = 0; hh < 2; hh++) {
                int r = warp_m + mt * 16 + hh * 8 + g;
                float mtile = fmaxf(red_m[r], red_m[128 + r]);
                float mnew  = fmaxf(row_m[r], mtile);
                float alpha = __expf(row_m[r] - mnew);
                float psum = 0.f;
                #pragma unroll
                for (int nt = 0; nt < 4; nt++) {
                    #pragma unroll
                    for (int j = 0; j < 2; j++) {
                        float p = __expf(sacc[mt][nt][hh * 2 + j] - mnew);
                        psum += p;
                        Ps[r * 68 + warp_n + nt * 8 + tg * 2 + j] = f2tf32(p);
                        oacc[mt][nt][hh * 2 + j] *= alpha;
                    }
                }
                psum += __shfl_xor_sync(0xffffffffu, psum, 1);
                psum += __shfl_xor_sync(0xffffffffu, psum, 2);
                if (tg == 0) red_l[colgrp * 128 + r] = psum;
            }
        }
        __syncthreads();

        // ---- update row stats (consistent values; single writer set) ----
        if (tid < 128) {
            int r = tid;
            float mtile = fmaxf(red_m[r], red_m[128 + r]);
            float mold = row_m[r];
            float mnew = fmaxf(mold, mtile);
            row_l[r] = __expf(mold - mnew) * row_l[r] + red_l[r] + red_l[128 + r];
            row_m[r] = mnew;
        }

        // ---- O += P @ V ----
        #pragma unroll
        for (int ks = 0; ks < 8; ks++) {
            const int kk = ks * 8;
            uint32_t af[2][4];
            #pragma unroll
            for (int mt = 0; mt < 2; mt++) {
                int rs = warp_m + mt * 16 + g;
                af[mt][0] = Ps[rs * 68 + kk + tg];
                af[mt][1] = Ps[(rs + 8) * 68 + kk + tg];
                af[mt][2] = Ps[rs * 68 + kk + tg + 4];
                af[mt][3] = Ps[(rs + 8) * 68 + kk + tg + 4];
            }
            uint32_t bf[4][2];
            #pragma unroll
            for (int nt = 0; nt < 4; nt++) {
                int cs = warp_n + nt * 8 + g;
                bf[nt][0] = Vs[cs * 68 + kk + tg];
                bf[nt][1] = Vs[cs * 68 + kk + tg + 4];
            }
            #pragma unroll
            for (int mt = 0; mt < 2; mt++)
                #pragma unroll
                for (int nt = 0; nt < 4; nt++)
                    mma_tf32(oacc[mt][nt], af[mt], bf[nt]);
        }
        __syncthreads();
    }

    // ---- normalize and store ----
    #pragma unroll
    for (int mt = 0; mt < 2; mt++) {
        #pragma unroll
        for (int hh = 0; hh < 2; hh++) {
            int r = warp_m + mt * 16 + hh * 8 + g;
            int t = q0 + r;
            if (t >= SEQ) continue;
            float inv = 1.f / row_l[r];
            #pragma unroll
            for (int nt = 0; nt < 4; nt++) {
                #pragma unroll
                for (int j = 0; j < 2; j++) {
                    int c = warp_n + nt * 8 + tg * 2 + j;
                    ATT[((long long)(b * SEQ + t)) * DM + h * HS + c] =
                        oacc[mt][nt][hh * 2 + j] * inv;
                }
            }
        }
    }
}

// ---------------------------------------------------------------------------
// LayerNorm: one block per row of 768
// ---------------------------------------------------------------------------
__global__ void __launch_bounds__(256)
ln_k(const float* __restrict__ x, float* __restrict__ out,
     const float* __restrict__ g, const float* __restrict__ b,
     long long strideIn, long long strideOut)
{
    long long r = blockIdx.x;
    const float* xr = x + r * strideIn;
    float* orow = out + r * strideOut;

    float s = 0.f, s2 = 0.f;
    for (int i = threadIdx.x; i < DM; i += 256) {
        float v = xr[i]; s += v; s2 += v * v;
    }
    for (int o = 16; o; o >>= 1) {
        s  += __shfl_down_sync(0xffffffffu, s,  o);
        s2 += __shfl_down_sync(0xffffffffu, s2, o);
    }
    __shared__ float shs[8], shs2[8];
    int w = threadIdx.x >> 5, ln = threadIdx.x & 31;
    if (ln == 0) { shs[w] = s; shs2[w] = s2; }
    __syncthreads();
    __shared__ float sh_m, sh_inv;
    if (threadIdx.x == 0) {
        float S = 0.f, S2 = 0.f;
        #pragma unroll
        for (int i = 0; i < 8; i++) { S += shs[i]; S2 += shs2[i]; }
        float m = S / (float)DM;
        float var = S2 / (float)DM - m * m;
        sh_m = m; sh_inv = rsqrtf(var + 1e-5f);
    }
    __syncthreads();
    float m = sh_m, inv = sh_inv;
    for (int i = threadIdx.x; i < DM; i += 256)
        orow[i] = (xr[i] - m) * inv * g[i] + b[i];
}

// ---------------------------------------------------------------------------
// Patchify / scatter / embed
// ---------------------------------------------------------------------------
__global__ void patchify_k(const float* __restrict__ img, float* __restrict__ P)
{
    int idx = blockIdx.x * blockDim.x + threadIdx.x;
    if (idx >= BATCH * NPATCH * DM) return;
    int d = idx % DM;
    int p = (idx / DM) % NPATCH;
    int b = idx / (DM * NPATCH);
    int c   = d % 3;
    int pix = d / 3;
    int px  = pix % PATCH, py = pix / PATCH;
    int pw  = p % 14,      ph = p / 14;
    int row = ph * PATCH + py, col = pw * PATCH + px;
    P[idx] = img[(((long long)b * IMG + row) * IMG + col) * 3 + c];
}

__global__ void scatter_patch_k(const float* __restrict__ G, float* __restrict__ X,
                                const float* __restrict__ pb,
                                const float* __restrict__ pos, int tokoff)
{
    int idx = blockIdx.x * blockDim.x + threadIdx.x;
    if (idx >= BATCH * NPATCH * DM) return;
    int d = idx % DM;
    int r = idx / DM;
    int b = r / NPATCH, p = r % NPATCH;
    int t = tokoff + p;
    X[((long long)b * SEQ + t) * DM + d] = G[idx] + pb[d] + pos[(long long)t * DM + d];
}

__global__ void embed_special_k(float* __restrict__ X,
                                const float* __restrict__ cls,
                                const float* __restrict__ goal,
                                const float* __restrict__ tok_emb,
                                const int*   __restrict__ txt,
                                const float* __restrict__ pos)
{
    int idx = blockIdx.x * blockDim.x + threadIdx.x;
    if (idx >= BATCH * 34 * DM) return;
    int d = idx % DM;
    int s = (idx / DM) % 34;
    int b = idx / (DM * 34);
    int t; float v;
    if (s == 0)      { t = 0;   v = cls[d];  }
    else if (s == 1) { t = 197; v = goal[d]; }
    else {
        t = 394 + (s - 2);
        v = tok_emb[(long long)txt[b * TB + (s - 2)] * DM + d];
    }
    X[((long long)b * SEQ + t) * DM + d] = v + pos[(long long)t * DM + d];
}

// ---------------------------------------------------------------------------
// Host driver
// ---------------------------------------------------------------------------
static inline dim3 ggrid(int M, int N, int BN, int bz)
{
    return dim3((unsigned)((N + BN - 1) / BN), (unsigned)((M + 127) / 128), (unsigned)bz);
}

extern "C" void kernel_launch(void* const* d_in, const int* in_sizes, int n_in,
                              void* d_out, int out_size)
{
    (void)in_sizes; (void)n_in; (void)out_size;

    const float* images    = (const float*)d_in[0];
    const float* goal_imgs = (const float*)d_in[1];
    const int*   goals_txt = (const int*)  d_in[2];
    const float* patch_W   = (const float*)d_in[3];
    const float* patch_b   = (const float*)d_in[4];
    const float* tok_emb   = (const float*)d_in[5];
    const float* pos_emb   = (const float*)d_in[6];
    const float* cls_tok   = (const float*)d_in[7];
    const float* goal_tok  = (const float*)d_in[8];
    const float* Wq        = (const float*)d_in[9];
    const float* Wk        = (const float*)d_in[10];
    const float* Wv        = (const float*)d_in[11];
    const float* Wo        = (const float*)d_in[12];
    const float* bo        = (const float*)d_in[13];
    const float* ln1_g     = (const float*)d_in[14];
    const float* ln1_b     = (const float*)d_in[15];
    const float* ln2_g     = (const float*)d_in[16];
    const float* ln2_b     = (const float*)d_in[17];
    const float* W1        = (const float*)d_in[18];
    const float* b1        = (const float*)d_in[19];
    const float* W2        = (const float*)d_in[20];
    const float* b2        = (const float*)d_in[21];
    const float* lnf_g     = (const float*)d_in[22];
    const float* lnf_b     = (const float*)d_in[23];
    const float* ah_W1     = (const float*)d_in[24];
    const float* ah_b1     = (const float*)d_in[25];
    const float* ah_W2     = (const float*)d_in[26];
    const float* ah_b2     = (const float*)d_in[27];
    float* out = (float*)d_out;

    float *X, *XN, *Qf, *Kf, *Vf, *ATT, *H, *P, *CLS, *HID;
    cudaGetSymbolAddress((void**)&X,   g_X);
    cudaGetSymbolAddress((void**)&XN,  g_XN);
    cudaGetSymbolAddress((void**)&Qf,  g_Q);
    cudaGetSymbolAddress((void**)&Kf,  g_K);
    cudaGetSymbolAddress((void**)&Vf,  g_V);
    cudaGetSymbolAddress((void**)&ATT, g_ATT);
    cudaGetSymbolAddress((void**)&H,   g_H);
    cudaGetSymbolAddress((void**)&P,   g_P);
    cudaGetSymbolAddress((void**)&CLS, g_CLS);
    cudaGetSymbolAddress((void**)&HID, g_HID);

    const int PTOT = BATCH * NPATCH * DM;
    const int FSMEM = FLASH_SMEM_WORDS * 4;
    cudaFuncSetAttribute(flash_attn_k, cudaFuncAttributeMaxDynamicSharedMemorySize, FSMEM);

    // --- Embedding ---------------------------------------------------------
    patchify_k<<<(PTOT + 255) / 256, 256>>>(images, P);
    gemm_tf32<128,false,false,false,false,false><<<ggrid(BATCH*NPATCH, DM, 128, 1), 256>>>(
        P, patch_W, H, nullptr, BATCH*NPATCH, DM, DM, DM, DM, DM, 1.f,
        1, 0,0, 0,0, 0,0);
    scatter_patch_k<<<(PTOT + 255) / 256, 256>>>(H, X, patch_b, pos_emb, 1);

    patchify_k<<<(PTOT + 255) / 256, 256>>>(goal_imgs, P);
    gemm_tf32<128,false,false,false,false,false><<<ggrid(BATCH*NPATCH, DM, 128, 1), 256>>>(
        P, patch_W, H, nullptr, BATCH*NPATCH, DM, DM, DM, DM, DM, 1.f,
        1, 0,0, 0,0, 0,0);
    scatter_patch_k<<<(PTOT + 255) / 256, 256>>>(H, X, patch_b, pos_emb, 198);

    embed_special_k<<<(BATCH*34*DM + 255) / 256, 256>>>(
        X, cls_tok, goal_tok, tok_emb, goals_txt, pos_emb);

    // --- Transformer layers ------------------------------------------------
    for (int l = 0; l < NL; l++) {
        const float* Wq_l  = Wq + (long long)l * NH * DM * HS;
        const float* Wk_l  = Wk + (long long)l * NH * DM * HS;
        const float* Wv_l  = Wv + (long long)l * NH * DM * HS;
        const float* Wo_l  = Wo + (long long)l * DM * DM;
        const float* bo_l  = bo + (long long)l * DM;
        const float* l1g   = ln1_g + (long long)l * DM;
        const float* l1b   = ln1_b + (long long)l * DM;
        const float* l2g   = ln2_g + (long long)l * DM;
        const float* l2b   = ln2_b + (long long)l * DM;
        const float* W1_l  = W1 + (long long)l * DM * MLPD;
        const float* b1_l  = b1 + (long long)l * MLPD;
        const float* W2_l  = W2 + (long long)l * MLPD * DM;
        const float* b2_l  = b2 + (long long)l * DM;

        ln_k<<<TOK, 256>>>(X, XN, l1g, l1b, DM, DM);

        // Q/K/V as single N=768 GEMMs with head-packed B addressing
        gemm_tf32<128,false,true,false,false,false><<<ggrid(TOK, DM, 128, 1), 256>>>(
            XN, Wq_l, Qf, nullptr, TOK, DM, DM, DM, DM*HS, DM, 1.f,
            1, 0,0, 0,0, 0,0);
        gemm_tf32<128,false,true,false,false,false><<<ggrid(TOK, DM, 128, 1), 256>>>(
            XN, Wk_l, Kf, nullptr, TOK, DM, DM, DM, DM*HS, DM, 1.f,
            1, 0,0, 0,0, 0,0);
        gemm_tf32<128,false,true,false,false,false><<<ggrid(TOK, DM, 128, 1), 256>>>(
            XN, Wv_l, Vf, nullptr, TOK, DM, DM, DM, DM*HS, DM, 1.f,
            1, 0,0, 0,0, 0,0);

        // Fused flash attention: ATT = softmax(scale*QK^T) @ V
        flash_attn_k<<<dim3(4, BATCH*NH), 256, FSMEM>>>(Qf, Kf, Vf, ATT);

        // X += ATT @ Wo + bo
        gemm_tf32<128,false,false,false,true,true><<<ggrid(TOK, DM, 128, 1), 256>>>(
            ATT, Wo_l, X, bo_l, TOK, DM, DM, DM, DM, DM, 1.f,
            1, 0,0, 0,0, 0,0);

        ln_k<<<TOK, 256>>>(X, XN, l2g, l2b, DM, DM);

        // H = relu(XN @ W1 + b1)
        gemm_tf32<128,false,false,true,false,true><<<ggrid(TOK, MLPD, 128, 1), 256>>>(
            XN, W1_l, H, b1_l, TOK, MLPD, DM, DM, MLPD, MLPD, 1.f,
            1, 0,0, 0,0, 0,0);

        // X += H @ W2 + b2
        gemm_tf32<128,false,false,false,true,true><<<ggrid(TOK, DM, 128, 1), 256>>>(
            H, W2_l, X, b2_l, TOK, DM, MLPD, MLPD, DM, DM, 1.f,
            1, 0,0, 0,0, 0,0);
    }

    // --- Final LN (cls rows only) + action head ---------------------------
    ln_k<<<BATCH, 256>>>(X, CLS, lnf_g, lnf_b, (long long)SEQ * DM, DM);

    gemm_tf32<128,false,false,true,false,true><<<ggrid(BATCH, 4*DM, 128, 1), 256>>>(
        CLS, ah_W1, HID, ah_b1, BATCH, 4*DM, DM, DM, 4*DM, 4*DM, 1.f,
        1, 0,0, 0,0, 0,0);

    gemm_tf32<64,false,false,false,false,true><<<ggrid(BATCH, AOUT, 64, 1), 256>>>(
        HID, ah_W2, out, ah_b2, BATCH, AOUT, 4*DM, 4*DM, AOUT, AOUT, 1.f,
        1, 0,0, 0,0, 0,0);
}